// round 4
// baseline (speedup 1.0000x reference)
#include <cuda_runtime.h>
#include <cuda_fp16.h>
#include <cstdint>

#define DI __device__ __forceinline__

constexpr int C    = 128;
constexpr int T    = 4096;
constexpr int R    = 4096;
constexpr int NCTX = 8;
constexpr int NT   = 32;     // 128-wide col tiles per 4096 row

// normalized features in fp16 (safe: values bounded by 1)
__device__ __align__(256) __half g_ft[T * C];                    // [t][k]   1 MB
__device__ __align__(256) __half g_fr[(size_t)NCTX * C * R];     // [n][k][r] 8 MB (L2-resident)
// fp16 exp(logit) spill, same layout as output
__device__ __align__(256) __half g_spill[(size_t)NCTX * T * R];  // 256 MB

// SMEM map
constexpr uint32_t SA   = 0;        // A tile 128x128 fp16, 256B rows, swizzled (32 KB)
constexpr uint32_t SB0  = 32768;    // B buf 0 (32 KB)
constexpr uint32_t SB1  = 65536;    // B buf 1 (32 KB)
constexpr uint32_t SRS  = 98304;    // 4 x 128 float partial rowsums
constexpr uint32_t SINV = 100352;   // 128 float inverse sums
constexpr uint32_t SMEM_SZ = 100864;

DI uint32_t s2u(const void* p) {
    uint32_t a;
    asm("{ .reg .u64 t; cvta.to.shared.u64 t, %1; cvt.u32.u64 %0, t; }" : "=r"(a) : "l"(p));
    return a;
}
DI void cpa16(uint32_t d, const void* g) {
    asm volatile("cp.async.cg.shared.global [%0], [%1], 16;" :: "r"(d), "l"(g));
}
DI void cpa_commit() { asm volatile("cp.async.commit_group;" ::: "memory"); }
template <int N> DI void cpa_wait() {
    asm volatile("cp.async.wait_group %0;" :: "n"(N) : "memory");
}

DI void ldsm4(uint32_t* r, uint32_t a) {
    asm volatile("ldmatrix.sync.aligned.m8n8.x4.shared.b16 {%0,%1,%2,%3}, [%4];"
                 : "=r"(r[0]), "=r"(r[1]), "=r"(r[2]), "=r"(r[3]) : "r"(a));
}
DI void ldsm4t(uint32_t* r, uint32_t a) {
    asm volatile("ldmatrix.sync.aligned.m8n8.x4.trans.shared.b16 {%0,%1,%2,%3}, [%4];"
                 : "=r"(r[0]), "=r"(r[1]), "=r"(r[2]), "=r"(r[3]) : "r"(a));
}
DI void mma16816(float* d, const uint32_t* a, const uint32_t* b) {
    asm volatile(
        "mma.sync.aligned.m16n8k16.row.col.f32.f16.f16.f32 "
        "{%0,%1,%2,%3}, {%4,%5,%6,%7}, {%8,%9}, {%0,%1,%2,%3};"
        : "+f"(d[0]), "+f"(d[1]), "+f"(d[2]), "+f"(d[3])
        : "r"(a[0]), "r"(a[1]), "r"(a[2]), "r"(a[3]), "r"(b[0]), "r"(b[1]));
}

// A tile: rows [t0,t0+128), k 0..127. 256B rows, chunk16 swizzle: c ^= row&7
DI void load_A(uint32_t sb, int t0, int tid) {
#pragma unroll
    for (int j = 0; j < 8; ++j) {
        int ch = tid + j * 256;
        int row = ch >> 4, c = ch & 15;
        int csw = c ^ (row & 7);
        cpa16(sb + SA + (uint32_t)(row * 256 + csw * 16),
              g_ft + (size_t)(t0 + row) * C + c * 8);
    }
}
// B tile: [k 0..127][n 0..127] fp16 from g_fr[n][k][rt*128 + n]
DI void load_B(uint32_t bb, int rt, int n, int tid) {
    const __half* src = g_fr + (size_t)n * C * R + (size_t)rt * 128;
#pragma unroll
    for (int j = 0; j < 8; ++j) {
        int ch = tid + j * 256;
        int k = ch >> 4, c = ch & 15;
        int csw = c ^ (k & 7);
        cpa16(bb + (uint32_t)(k * 256 + csw * 16), src + (size_t)k * R + c * 8);
    }
}

__global__ void __launch_bounds__(256, 2) affinity_main(float* __restrict__ out) {
    extern __shared__ char smem[];
    uint32_t sb = s2u(smem);
    int tid = threadIdx.x, l = tid & 31, wid = tid >> 5;
    int wm = wid & 1, wn = wid >> 1;                  // 2 x 4 warp grid (64M x 32N)
    int n = blockIdx.x >> 5, t0 = (blockIdx.x & 31) << 7;

    // ldmatrix per-lane address components
    int moff = (l & 7) + ((l >> 3) & 1) * 8;          // row-in-16 for lane
    int cgrp = l >> 4;                                // chunk +0/+1 (k-halves / n-halves)
    int rm = l & 7;                                   // swizzle key
    uint32_t aRow[4];
#pragma unroll
    for (int mf = 0; mf < 4; ++mf) aRow[mf] = (uint32_t)((wm * 64 + mf * 16 + moff) * 256);
    uint32_t bOff[2];
#pragma unroll
    for (int nf = 0; nf < 2; ++nf)
        bOff[nf] = (uint32_t)(moff * 256 + (((wn * 4 + nf * 2 + cgrp) ^ rm) << 4));

    // prologue
    load_A(sb, t0, tid);
    load_B(sb + SB0, 0, n, tid);
    cpa_commit();

    float rs[8];
#pragma unroll
    for (int i = 0; i < 8; ++i) rs[i] = 0.f;

    __half* spill_base = g_spill + ((size_t)n * T + (size_t)t0) * R;

    // ---- single GEMM pass: exp -> fp16 spill + fp32 rowsums ----
#pragma unroll 1
    for (int t = 0; t < NT; ++t) {
        if (t + 1 < NT) {
            load_B(sb + (((t + 1) & 1) ? SB1 : SB0), t + 1, n, tid);
            cpa_commit();
            cpa_wait<1>();
        } else {
            cpa_wait<0>();
        }
        __syncthreads();

        float acc[4][4][4];
#pragma unroll
        for (int mf = 0; mf < 4; ++mf)
#pragma unroll
            for (int j8 = 0; j8 < 4; ++j8)
#pragma unroll
                for (int r = 0; r < 4; ++r) acc[mf][j8][r] = 0.f;

        uint32_t bb = sb + ((t & 1) ? SB1 : SB0);
#pragma unroll
        for (int ks = 0; ks < 8; ++ks) {
            uint32_t af[4][4], bf[2][4];
#pragma unroll
            for (int mf = 0; mf < 4; ++mf)
                ldsm4(af[mf], sb + SA + aRow[mf] + (uint32_t)(((ks * 2 + cgrp) ^ rm) << 4));
#pragma unroll
            for (int nf = 0; nf < 2; ++nf)
                ldsm4t(bf[nf], bb + (uint32_t)(ks * 4096) + bOff[nf]);
#pragma unroll
            for (int mf = 0; mf < 4; ++mf)
#pragma unroll
                for (int j8 = 0; j8 < 4; ++j8)
                    mma16816(acc[mf][j8], af[mf], &bf[j8 >> 1][(j8 & 1) * 2]);
        }

        // epilogue: exp, rowsum accumulate, fp16 spill
        int colg = t * 128 + wn * 32 + (l & 3) * 2;
#pragma unroll
        for (int mf = 0; mf < 4; ++mf) {
            __half* rowp = spill_base + (size_t)(wm * 64 + mf * 16 + (l >> 2)) * R + colg;
#pragma unroll
            for (int j8 = 0; j8 < 4; ++j8) {
                float e0 = __expf(acc[mf][j8][0]);
                float e1 = __expf(acc[mf][j8][1]);
                float e2 = __expf(acc[mf][j8][2]);
                float e3 = __expf(acc[mf][j8][3]);
                rs[mf * 2 + 0] += e0 + e1;
                rs[mf * 2 + 1] += e2 + e3;
                *reinterpret_cast<__half2*>(rowp + j8 * 8)          = __floats2half2_rn(e0, e1);
                *reinterpret_cast<__half2*>(rowp + 8 * R + j8 * 8)  = __floats2half2_rn(e2, e3);
            }
        }
        __syncthreads();
    }

    // ---- rowsum reduction -> sinv ----
#pragma unroll
    for (int i = 0; i < 8; ++i) {
        rs[i] += __shfl_xor_sync(0xFFFFFFFFu, rs[i], 1);
        rs[i] += __shfl_xor_sync(0xFFFFFFFFu, rs[i], 2);
    }
    float* rsp = (float*)(smem + SRS);
    if ((l & 3) == 0) {
#pragma unroll
        for (int mf = 0; mf < 4; ++mf)
#pragma unroll
            for (int h = 0; h < 2; ++h) {
                int row = wm * 64 + mf * 16 + (l >> 2) + h * 8;
                rsp[wn * 128 + row] = rs[mf * 2 + h];
            }
    }
    __syncthreads();
    float* sinv = (float*)(smem + SINV);
    if (tid < 128) {
        float s = rsp[tid] + rsp[128 + tid] + rsp[256 + tid] + rsp[384 + tid];
        sinv[tid] = 1.0f / s;
    }
    __syncthreads();   // also orders the spill global writes within the CTA

    // ---- streaming scale pass: out = spill * sinv[row] ----
    {
        const __half* sp = spill_base;
        float* op = out + ((size_t)n * T + (size_t)t0) * R;
        constexpr int CHUNKS = 128 * R / 8;   // 8 halves per chunk
#pragma unroll 1
        for (int i = tid; i < CHUNKS; i += 256) {
            float is = sinv[i >> 9];          // 512 chunks per row
            uint4 raw = *reinterpret_cast<const uint4*>(sp + (size_t)i * 8);
            const __half2* hp = reinterpret_cast<const __half2*>(&raw);
            float2 a0 = __half22float2(hp[0]);
            float2 a1 = __half22float2(hp[1]);
            float2 a2 = __half22float2(hp[2]);
            float2 a3 = __half22float2(hp[3]);
            float4 o0, o1;
            o0.x = a0.x * is; o0.y = a0.y * is; o0.z = a1.x * is; o0.w = a1.y * is;
            o1.x = a2.x * is; o1.y = a2.y * is; o1.z = a3.x * is; o1.w = a3.y * is;
            *reinterpret_cast<float4*>(op + (size_t)i * 8)     = o0;
            *reinterpret_cast<float4*>(op + (size_t)i * 8 + 4) = o1;
        }
    }
}

// ---------------- fused normalization (one kernel -> 2 launches/call) ----------------
__global__ void norm_all_kernel(const float* __restrict__ ft, const float* __restrict__ fr) {
    if (blockIdx.x < 512) {
        int row = blockIdx.x * 8 + (threadIdx.x >> 5);
        int lid = threadIdx.x & 31;
        const float* p = ft + (size_t)row * C;
        float v[4], s = 0.f;
#pragma unroll
        for (int j = 0; j < 4; ++j) { v[j] = p[lid + 32 * j]; s += v[j] * v[j]; }
#pragma unroll
        for (int o = 16; o > 0; o >>= 1) s += __shfl_xor_sync(0xFFFFFFFFu, s, o);
        float inv = 1.0f / fmaxf(sqrtf(s), 1e-12f);
#pragma unroll
        for (int j = 0; j < 4; ++j)
            g_ft[(size_t)row * C + lid + 32 * j] = __float2half_rn(v[j] * inv);
    } else {
        int idx = (blockIdx.x - 512) * 256 + threadIdx.x;   // 0..32767
        int n = idx >> 12, r = idx & (R - 1);
        const float* p = fr + (size_t)n * C * R + r;
        float s = 0.f;
#pragma unroll 4
        for (int k = 0; k < C; ++k) { float v = p[(size_t)k * R]; s += v * v; }
        float inv = 1.0f / fmaxf(sqrtf(s), 1e-12f);
#pragma unroll 4
        for (int k = 0; k < C; ++k)
            g_fr[(size_t)n * C * R + (size_t)k * R + r] = __float2half_rn(p[(size_t)k * R] * inv);
    }
}

extern "C" void kernel_launch(void* const* d_in, const int* in_sizes, int n_in,
                              void* d_out, int out_size) {
    const float* feat_tar  = (const float*)d_in[0];
    const float* feat_refs = (const float*)d_in[1];
    float* out = (float*)d_out;

    cudaFuncSetAttribute(affinity_main, cudaFuncAttributeMaxDynamicSharedMemorySize, SMEM_SZ);

    norm_all_kernel<<<512 + 128, 256>>>(feat_tar, feat_refs);
    affinity_main<<<NCTX * NT, 256, SMEM_SZ>>>(out);
}

// round 5
// speedup vs baseline: 1.4060x; 1.4060x over previous
#include <cuda_runtime.h>
#include <cuda_fp16.h>
#include <cstdint>

#define DI __device__ __forceinline__

constexpr int C    = 128;
constexpr int T    = 4096;
constexpr int R    = 4096;
constexpr int NCTX = 8;
constexpr int NT   = 32;     // 128-wide col tiles per 4096 row
constexpr int NG   = 2 * NT; // two passes, continuous tile counter

// normalized features in fp16 (values bounded by 1 -> fp16-exact enough)
__device__ __align__(256) __half g_ft[T * C];                    // [t][k]   1 MB
__device__ __align__(256) __half g_fr[(size_t)NCTX * C * R];     // [n][k][r] 8 MB (L2-resident)

// SMEM map: 3-stage B ring + one-time A staging + reduction scratch
constexpr uint32_t SB_ST  = 0;        // 3 x 32 KB B buffers
constexpr uint32_t SB_SZ  = 32768;
constexpr uint32_t SA_ST  = 98304;    // A staging 32 KB (used once)
constexpr uint32_t SRS    = 131072;   // 4 x 128 float partial rowsums
constexpr uint32_t SINV   = 133120;   // 128 float inverse sums
constexpr uint32_t SMEM_SZ = 133632;

DI uint32_t s2u(const void* p) {
    uint32_t a;
    asm("{ .reg .u64 t; cvta.to.shared.u64 t, %1; cvt.u32.u64 %0, t; }" : "=r"(a) : "l"(p));
    return a;
}
DI void cpa16(uint32_t d, const void* g) {
    asm volatile("cp.async.cg.shared.global [%0], [%1], 16;" :: "r"(d), "l"(g));
}
DI void cpa_commit() { asm volatile("cp.async.commit_group;" ::: "memory"); }
template <int N> DI void cpa_wait() {
    asm volatile("cp.async.wait_group %0;" :: "n"(N) : "memory");
}

DI void ldsm4(uint32_t* r, uint32_t a) {
    asm volatile("ldmatrix.sync.aligned.m8n8.x4.shared.b16 {%0,%1,%2,%3}, [%4];"
                 : "=r"(r[0]), "=r"(r[1]), "=r"(r[2]), "=r"(r[3]) : "r"(a));
}
DI void ldsm4t(uint32_t* r, uint32_t a) {
    asm volatile("ldmatrix.sync.aligned.m8n8.x4.trans.shared.b16 {%0,%1,%2,%3}, [%4];"
                 : "=r"(r[0]), "=r"(r[1]), "=r"(r[2]), "=r"(r[3]) : "r"(a));
}
DI void mma16816(float* d, const uint32_t* a, const uint32_t* b) {
    asm volatile(
        "mma.sync.aligned.m16n8k16.row.col.f32.f16.f16.f32 "
        "{%0,%1,%2,%3}, {%4,%5,%6,%7}, {%8,%9}, {%0,%1,%2,%3};"
        : "+f"(d[0]), "+f"(d[1]), "+f"(d[2]), "+f"(d[3])
        : "r"(a[0]), "r"(a[1]), "r"(a[2]), "r"(a[3]), "r"(b[0]), "r"(b[1]));
}

// A tile: rows [t0,t0+128), k 0..127. 256B rows, chunk16 swizzle: c ^= row&7
DI void load_A(uint32_t base, int t0, int tid) {
#pragma unroll
    for (int j = 0; j < 8; ++j) {
        int ch = tid + j * 256;
        int row = ch >> 4, c = ch & 15;
        int csw = c ^ (row & 7);
        cpa16(base + (uint32_t)(row * 256 + csw * 16),
              g_ft + (size_t)(t0 + row) * C + c * 8);
    }
}
// B tile: [k 0..127][n 0..127] fp16 from g_fr[n][k][rt*128 + c*8]
DI void load_B(uint32_t bb, int rt, int n, int tid) {
    const __half* src = g_fr + (size_t)n * C * R + (size_t)rt * 128;
#pragma unroll
    for (int j = 0; j < 8; ++j) {
        int ch = tid + j * 256;
        int k = ch >> 4, c = ch & 15;
        int csw = c ^ (k & 7);
        cpa16(bb + (uint32_t)(k * 256 + csw * 16), src + (size_t)k * R + c * 8);
    }
}

__global__ void __launch_bounds__(256, 1) affinity_main(float* __restrict__ out) {
    extern __shared__ char smem[];
    uint32_t sb = s2u(smem);
    int tid = threadIdx.x, l = tid & 31, wid = tid >> 5;
    int wm = wid & 1, wn = wid >> 1;                  // 2 x 4 warp grid (64M x 32N)
    int n = blockIdx.x >> 5, t0 = (blockIdx.x & 31) << 7;

    int moff = (l & 7) + ((l >> 3) & 1) * 8;          // row-in-16 for this lane
    int cgrp = l >> 4;                                // +0/+1 chunk (16B)
    int rm = l & 7;                                   // swizzle key
    uint32_t aRow[4];
#pragma unroll
    for (int mf = 0; mf < 4; ++mf) aRow[mf] = (uint32_t)((wm * 64 + mf * 16 + moff) * 256);
    uint32_t bOff[2];
#pragma unroll
    for (int nf = 0; nf < 2; ++nf)
        bOff[nf] = (uint32_t)(moff * 256 + (((wn * 4 + nf * 2 + cgrp) ^ rm) << 4));

    // prologue: A stage (group 0), B tile0 (group 1), B tile1 (group 2)
    load_A(sb + SA_ST, t0, tid);
    cpa_commit();
    load_B(sb + SB_ST, 0, n, tid);
    cpa_commit();
    load_B(sb + SB_ST + SB_SZ, 1, n, tid);
    cpa_commit();
    cpa_wait<2>();            // A resident
    __syncthreads();

    // A tile -> registers, once. 128 regs; eliminates 2/3 of per-tile smem reads.
    uint32_t aR[8][4][4];
#pragma unroll
    for (int ks = 0; ks < 8; ++ks)
#pragma unroll
        for (int mf = 0; mf < 4; ++mf)
            ldsm4(aR[ks][mf], sb + SA_ST + aRow[mf] + (uint32_t)(((ks * 2 + cgrp) ^ rm) << 4));

    float rsv[8];             // pass0: rowsum accum; pass1: per-row inverse sums
#pragma unroll
    for (int i = 0; i < 8; ++i) rsv[i] = 0.f;

#pragma unroll 1
    for (int pass = 0; pass < 2; ++pass) {
#pragma unroll 1
        for (int t = 0; t < NT; ++t) {
            int g = pass * NT + t;
            if (g + 2 < NG) {
                load_B(sb + SB_ST + (uint32_t)((g + 2) % 3) * SB_SZ, (g + 2) & (NT - 1), n, tid);
                cpa_commit();
                cpa_wait<2>();
            } else if (g + 1 < NG) {
                cpa_wait<1>();
            } else {
                cpa_wait<0>();
            }
            __syncthreads();

            float acc[4][4][4];
#pragma unroll
            for (int mf = 0; mf < 4; ++mf)
#pragma unroll
                for (int j8 = 0; j8 < 4; ++j8)
#pragma unroll
                    for (int r = 0; r < 4; ++r) acc[mf][j8][r] = 0.f;

            uint32_t bb = sb + SB_ST + (uint32_t)(g % 3) * SB_SZ;
#pragma unroll
            for (int ks = 0; ks < 8; ++ks) {
                uint32_t bf[2][4];
                ldsm4t(bf[0], bb + (uint32_t)(ks * 4096) + bOff[0]);
                ldsm4t(bf[1], bb + (uint32_t)(ks * 4096) + bOff[1]);
#pragma unroll
                for (int mf = 0; mf < 4; ++mf)
#pragma unroll
                    for (int j8 = 0; j8 < 4; ++j8)
                        mma16816(acc[mf][j8], aR[ks][mf], &bf[j8 >> 1][(j8 & 1) * 2]);
            }

            if (pass == 0) {
#pragma unroll
                for (int mf = 0; mf < 4; ++mf)
#pragma unroll
                    for (int j8 = 0; j8 < 4; ++j8) {
                        rsv[mf * 2 + 0] += __expf(acc[mf][j8][0]) + __expf(acc[mf][j8][1]);
                        rsv[mf * 2 + 1] += __expf(acc[mf][j8][2]) + __expf(acc[mf][j8][3]);
                    }
            } else {
                int colg = t * 128 + wn * 32 + (l & 3) * 2;
#pragma unroll
                for (int mf = 0; mf < 4; ++mf) {
                    size_t rowa = ((size_t)n * T + (size_t)(t0 + wm * 64 + mf * 16 + (l >> 2))) * R;
                    float iv0 = rsv[mf * 2], iv1 = rsv[mf * 2 + 1];
#pragma unroll
                    for (int j8 = 0; j8 < 4; ++j8) {
                        float2 v0, v1;
                        v0.x = __expf(acc[mf][j8][0]) * iv0;
                        v0.y = __expf(acc[mf][j8][1]) * iv0;
                        v1.x = __expf(acc[mf][j8][2]) * iv1;
                        v1.y = __expf(acc[mf][j8][3]) * iv1;
                        *reinterpret_cast<float2*>(out + rowa + colg + j8 * 8)         = v0;
                        *reinterpret_cast<float2*>(out + rowa + 8 * R + colg + j8 * 8) = v1;
                    }
                }
            }
            __syncthreads();   // protects B ring buffer reuse (distance 3)
        }

        if (pass == 0) {
            // reduce rowsums: 4 lanes/row -> smem -> 4 wn columns -> inverse
#pragma unroll
            for (int i = 0; i < 8; ++i) {
                rsv[i] += __shfl_xor_sync(0xFFFFFFFFu, rsv[i], 1);
                rsv[i] += __shfl_xor_sync(0xFFFFFFFFu, rsv[i], 2);
            }
            float* rsp = (float*)(smem + SRS);
            if ((l & 3) == 0) {
#pragma unroll
                for (int mf = 0; mf < 4; ++mf)
#pragma unroll
                    for (int h = 0; h < 2; ++h) {
                        int row = wm * 64 + mf * 16 + (l >> 2) + h * 8;
                        rsp[wn * 128 + row] = rsv[mf * 2 + h];
                    }
            }
            __syncthreads();
            float* sinv = (float*)(smem + SINV);
            if (tid < 128) {
                float s = rsp[tid] + rsp[128 + tid] + rsp[256 + tid] + rsp[384 + tid];
                sinv[tid] = 1.0f / s;
            }
            __syncthreads();
#pragma unroll
            for (int mf = 0; mf < 4; ++mf)
#pragma unroll
                for (int h = 0; h < 2; ++h)
                    rsv[mf * 2 + h] = sinv[wm * 64 + mf * 16 + (l >> 2) + h * 8];
        }
    }
}

// ---------------- fused normalization ----------------
__global__ void norm_all_kernel(const float* __restrict__ ft, const float* __restrict__ fr) {
    if (blockIdx.x < 512) {
        int row = blockIdx.x * 8 + (threadIdx.x >> 5);
        int lid = threadIdx.x & 31;
        const float* p = ft + (size_t)row * C;
        float v[4], s = 0.f;
#pragma unroll
        for (int j = 0; j < 4; ++j) { v[j] = p[lid + 32 * j]; s += v[j] * v[j]; }
#pragma unroll
        for (int o = 16; o > 0; o >>= 1) s += __shfl_xor_sync(0xFFFFFFFFu, s, o);
        float inv = 1.0f / fmaxf(sqrtf(s), 1e-12f);
#pragma unroll
        for (int j = 0; j < 4; ++j)
            g_ft[(size_t)row * C + lid + 32 * j] = __float2half_rn(v[j] * inv);
    } else {
        int idx = (blockIdx.x - 512) * 256 + threadIdx.x;   // 0..32767
        int n = idx >> 12, r = idx & (R - 1);
        const float* p = fr + (size_t)n * C * R + r;
        float s = 0.f;
#pragma unroll 4
        for (int k = 0; k < C; ++k) { float v = p[(size_t)k * R]; s += v * v; }
        float inv = 1.0f / fmaxf(sqrtf(s), 1e-12f);
#pragma unroll 4
        for (int k = 0; k < C; ++k)
            g_fr[(size_t)n * C * R + (size_t)k * R + r] = __float2half_rn(p[(size_t)k * R] * inv);
    }
}

extern "C" void kernel_launch(void* const* d_in, const int* in_sizes, int n_in,
                              void* d_out, int out_size) {
    const float* feat_tar  = (const float*)d_in[0];
    const float* feat_refs = (const float*)d_in[1];
    float* out = (float*)d_out;

    cudaFuncSetAttribute(affinity_main, cudaFuncAttributeMaxDynamicSharedMemorySize, SMEM_SZ);

    norm_all_kernel<<<512 + 128, 256>>>(feat_tar, feat_refs);
    affinity_main<<<NCTX * NT, 256, SMEM_SZ>>>(out);
}